// round 13
// baseline (speedup 1.0000x reference)
#include <cuda_runtime.h>
#include <cuda_bf16.h>
#include <math.h>
#include <stdint.h>

#define NN  100000
#define NE  1600000
#define DD  128
#define NG  64
#define PHH 32
#define NTILES 782   // ceil(NN/128)
#define NSB 98       // scan blocks

// ---------------- device scratch (no allocations allowed) ----------------
__device__ int      g_deg[NN];
__device__ int      g_off[NN + 1];
__device__ int      g_fill[NN];
__device__ unsigned g_agg[128];            // lookback aggregates (bit31 = valid)
__device__ int      g_csr[NE];
__device__ int      g_gcnt[NG];
__device__ float    g_norm[NN];
__device__ float    g_pooled[NG * DD];
__device__ uint16_t g_fb[NN * DD];         // bf16 feature, unscaled (GEMM f0)
__device__ uint8_t  g_fs[NN * DD];         // fp8 norm⊙feature (L1 gather)
__device__ uint8_t  g_xs[NN * DD];         // fp8 norm⊙x1 (L2 gather)
__device__ uint16_t g_hb[NN * DD];         // bf16 hs (GEMM A operand)
__device__ uint16_t g_w1b[2][DD * DD];     // effective W1 per layer, [n][k], bf16
__device__ uint16_t g_w2b[2][DD * DD];     // effective W2 (x0.5) per layer, bf16

// ---------------- helpers ----------------
__device__ __forceinline__ uint32_t smem_u32(const void* p) {
    uint32_t a;
    asm("{ .reg .u64 t; cvta.to.shared.u64 t, %1; cvt.u32.u64 %0, t; }"
        : "=r"(a) : "l"(p));
    return a;
}

__device__ __forceinline__ uint32_t bf2pack(float lo, float hi) {
    uint32_t p;
    asm("cvt.rn.bf16x2.f32 %0, %1, %2;" : "=r"(p) : "f"(hi), "f"(lo));
    return p;
}

__device__ __forceinline__ uint16_t bf1(float v) {
    return (uint16_t)(bf2pack(v, 0.f) & 0xFFFFu);
}

// pack 2 floats -> e4m3x2 (lo in low byte)
__device__ __forceinline__ uint16_t fp8pack(float lo, float hi) {
    uint16_t r;
    asm("cvt.rn.satfinite.e4m3x2.f32 %0, %1, %2;" : "=h"(r) : "f"(hi), "f"(lo));
    return r;
}

// 4 fp8 (one u32) -> two half2
__device__ __forceinline__ void fp8x4_to_h2x2(uint32_t w, uint32_t& h01, uint32_t& h23) {
    asm("{ .reg .b16 lo, hi;\n\t"
        "mov.b32 {lo, hi}, %2;\n\t"
        "cvt.rn.f16x2.e4m3x2 %0, lo;\n\t"
        "cvt.rn.f16x2.e4m3x2 %1, hi; }"
        : "=r"(h01), "=r"(h23) : "r"(w));
}

__device__ __forceinline__ uint32_t hadd2(uint32_t a, uint32_t b) {
    uint32_t r;
    asm("add.f16x2 %0, %1, %2;" : "=r"(r) : "r"(a), "r"(b));
    return r;
}

__device__ __forceinline__ float2 h2f(uint32_t h) {
    float2 f;
    asm("{ .reg .b16 lo, hi;\n\t"
        "mov.b32 {lo, hi}, %2;\n\t"
        "cvt.f32.f16 %0, lo;\n\t"
        "cvt.f32.f16 %1, hi; }"
        : "=f"(f.x), "=f"(f.y) : "r"(h));
    return f;
}

__device__ __forceinline__ void cpa16(uint32_t dst, const void* src) {
    asm volatile("cp.async.cg.shared.global [%0], [%1], 16;"
                 :: "r"(dst), "l"(src) : "memory");
}

__device__ __forceinline__ void ldsm4(uint32_t* r, uint32_t addr) {
    asm volatile("ldmatrix.sync.aligned.m8n8.x4.shared.b16 {%0,%1,%2,%3}, [%4];"
                 : "=r"(r[0]), "=r"(r[1]), "=r"(r[2]), "=r"(r[3]) : "r"(addr));
}

__device__ __forceinline__ void mma16(float* c, const uint32_t* a,
                                      uint32_t b0, uint32_t b1) {
    asm volatile(
        "mma.sync.aligned.m16n8k16.row.col.f32.bf16.bf16.f32 "
        "{%0,%1,%2,%3}, {%4,%5,%6,%7}, {%8,%9}, {%0,%1,%2,%3};"
        : "+f"(c[0]), "+f"(c[1]), "+f"(c[2]), "+f"(c[3])
        : "r"(a[0]), "r"(a[1]), "r"(a[2]), "r"(a[3]), "r"(b0), "r"(b1));
}

__device__ __forceinline__ float bflo(uint32_t u) { return __uint_as_float(u << 16); }
__device__ __forceinline__ float bfhi(uint32_t u) { return __uint_as_float(u & 0xFFFF0000u); }

// ---------------- setup ----------------
__global__ void k_zero() {
    int i = blockIdx.x * blockDim.x + threadIdx.x;
    if (i < NN) { g_deg[i] = 0; g_fill[i] = 0; }
    if (i < NG * DD) g_pooled[i] = 0.f;
    if (i < NG) g_gcnt[i] = 0;
    if (i < 128) g_agg[i] = 0u;
}

// fused: degree count + bf16 feature copy + effective-weight prep
__global__ void k_pre(const float* __restrict__ feat, const int* __restrict__ dst,
                      const float* __restrict__ w11, const float* __restrict__ w21,
                      const float* __restrict__ w12, const float* __restrict__ w22) {
    int i = blockIdx.x * blockDim.x + threadIdx.x;
    if (i < NE) atomicAdd(&g_deg[dst[i]], 1);
    if (i < NN * DD / 4) {
        float4 v = __ldg((const float4*)feat + i);
        uint2 b;
        b.x = bf2pack(v.x, v.y);
        b.y = bf2pack(v.z, v.w);
        ((uint2*)g_fb)[i] = b;
    }
    if (i < DD * DD) {
        const float B1 = 0.6931471805599453f;  // log 2
        const float B2 = 0.4054651081081644f;  // log 1.5
        int n = i >> 7, k = i & 127;
        float ikn = (k == n) ? 1.f : 0.f;
        g_w1b[0][n * DD + k] = bf1(B1 * w11[k * DD + n] + (1.f - B1) * ikn);
        g_w2b[0][n * DD + k] = bf1(0.5f * (B1 * w21[k * DD + n] + (1.f - B1) * ikn));
        g_w1b[1][n * DD + k] = bf1(B2 * w12[k * DD + n] + (1.f - B2) * ikn);
        g_w2b[1][n * DD + k] = bf1(0.5f * (B2 * w22[k * DD + n] + (1.f - B2) * ikn));
    }
}

// fused scan: warp-shuffle block scan + lookback + norm/gcnt
__global__ void k_scan(const int* __restrict__ gids) {
    __shared__ int wsum[32];
    __shared__ int blockoff;
    int b = blockIdx.x, t = threadIdx.x;
    int wid = t >> 5, ln = t & 31;
    int i = b * 1024 + t;
    int v = (i < NN) ? g_deg[i] : 0;
    // warp inclusive scan
    int x = v;
    #pragma unroll
    for (int o = 1; o < 32; o <<= 1) {
        int y = __shfl_up_sync(0xFFFFFFFFu, x, o);
        if (ln >= o) x += y;
    }
    if (ln == 31) wsum[wid] = x;
    __syncthreads();
    if (wid == 0) {
        int s = wsum[ln];
        #pragma unroll
        for (int o = 1; o < 32; o <<= 1) {
            int y = __shfl_up_sync(0xFFFFFFFFu, s, o);
            if (ln >= o) s += y;
        }
        wsum[ln] = s;
    }
    __syncthreads();
    int incl = x + (wid ? wsum[wid - 1] : 0);   // block-inclusive scan of v
    if (t == 1023)
        atomicExch(&g_agg[b], 0x80000000u | (unsigned)incl);
    if (t < 32) {
        int sum = 0;
        for (int base = 0; base < b; base += 32) {
            int idx = base + t;
            unsigned val = 0;
            if (idx < b) {
                do { val = *(volatile unsigned*)&g_agg[idx]; }
                while (!(val & 0x80000000u));
            }
            sum += (int)(val & 0x7FFFFFFFu);
        }
        #pragma unroll
        for (int o = 16; o > 0; o >>= 1)
            sum += __shfl_down_sync(0xFFFFFFFFu, sum, o);
        if (t == 0) blockoff = sum;
    }
    __syncthreads();
    if (i < NN) {
        g_off[i] = blockoff + incl - v;
        g_norm[i] = rsqrtf((float)(v + 1));   // +1 self loop
        atomicAdd(&g_gcnt[gids[i]], 1);
    }
    if (i == NN) g_off[NN] = NE;
}

// fused: CSR fill + fp8 scaled feature (norm ⊙ feature) for the L1 gather
__global__ void k_fill(const int* __restrict__ src, const int* __restrict__ dst) {
    int i = blockIdx.x * blockDim.x + threadIdx.x;
    if (i < NE) {
        int d = dst[i];
        int p = g_off[d] + atomicAdd(&g_fill[d], 1);
        g_csr[p] = src[i];
    }
    if (i < NN * DD / 4) {
        int node = i >> 5;                  // 32 quads per row
        float nrm = g_norm[node];
        uint2 b = ((const uint2*)g_fb)[i];
        uint16_t p0 = fp8pack(bflo(b.x) * nrm, bfhi(b.x) * nrm);
        uint16_t p1 = fp8pack(bflo(b.y) * nrm, bfhi(b.y) * nrm);
        ((uint32_t*)g_fs)[i] = (uint32_t)p0 | ((uint32_t)p1 << 16);
    }
}

// ---- SpMM (fp8 gather, half2 accumulate): hs = bf16(0.5*nrm*(x̃[n]+Σx̃[src]))
// 16-lane node groups (uint2 = 8 fp8/lane), 8-edge unroll.
__global__ void k_spmm(const uint8_t* __restrict__ fin, uint16_t* __restrict__ fout) {
    int gt = blockIdx.x * blockDim.x + threadIdx.x;
    int node = gt >> 4, lane = gt & 15;
    if (node >= NN) return;
    const uint2* F = (const uint2*)fin;   // row = 128B = 16 x uint2
    uint2 a = __ldg(F + (size_t)node * 16 + lane);   // self loop (pre-scaled)
    uint32_t h[4];
    fp8x4_to_h2x2(a.x, h[0], h[1]);
    fp8x4_to_h2x2(a.y, h[2], h[3]);

    int beg = g_off[node], end = g_off[node + 1];
    int e = beg;
    for (; e + 8 <= end; e += 8) {
        uint2 v[8];
        #pragma unroll
        for (int j = 0; j < 8; j++) {
            int s = __ldg(g_csr + e + j);
            v[j] = __ldg(F + (size_t)s * 16 + lane);
        }
        #pragma unroll
        for (int j = 0; j < 8; j++) {
            uint32_t c0, c1, c2, c3;
            fp8x4_to_h2x2(v[j].x, c0, c1);
            fp8x4_to_h2x2(v[j].y, c2, c3);
            h[0] = hadd2(h[0], c0);
            h[1] = hadd2(h[1], c1);
            h[2] = hadd2(h[2], c2);
            h[3] = hadd2(h[3], c3);
        }
    }
    for (; e < end; e++) {
        int s = __ldg(g_csr + e);
        uint2 v0 = __ldg(F + (size_t)s * 16 + lane);
        uint32_t c0, c1, c2, c3;
        fp8x4_to_h2x2(v0.x, c0, c1);
        fp8x4_to_h2x2(v0.y, c2, c3);
        h[0] = hadd2(h[0], c0);
        h[1] = hadd2(h[1], c1);
        h[2] = hadd2(h[2], c2);
        h[3] = hadd2(h[3], c3);
    }
    float sc = 0.5f * g_norm[node];
    float2 f0 = h2f(h[0]), f1 = h2f(h[1]), f2 = h2f(h[2]), f3 = h2f(h[3]);
    uint4 o;
    o.x = bf2pack(f0.x * sc, f0.y * sc);
    o.y = bf2pack(f1.x * sc, f1.y * sc);
    o.z = bf2pack(f2.x * sc, f2.y * sc);
    o.w = bf2pack(f3.x * sc, f3.y * sc);
    ((uint4*)fout)[(size_t)node * 16 + lane] = o;
}

// ---- bf16 mma.sync GEMM: relu(hs@W1e + f0@W2e + b) ------------------------
// BM=128, BN=64, K=256 (hs|f0), BK=64. FULL 4-stage prefetch: all 4 chunks'
// cp.async groups issued up front (96KB smem), drained with wait_group 3..0.
// 8 warps (warp tile 32x32), 2 CTAs/SM.
// MODE 0: write fp8 norm⊙x1 (feeds L2 gather). MODE 1: pool into g_pooled.
template <int MODE>
__global__ void __launch_bounds__(256, 2)
k_mma(const uint16_t* __restrict__ Ahs, const uint16_t* __restrict__ Af0,
      const uint16_t* __restrict__ Bw1, const uint16_t* __restrict__ Bw2,
      const float* __restrict__ bias, uint8_t* __restrict__ x8out,
      const int* __restrict__ gids) {
    extern __shared__ float smem[];   // 4 stages x (A 16KB + B 8KB)
    uint32_t sb = smem_u32(smem);
    int t = threadIdx.x, lane = t & 31, w = t >> 5;
    int wm = (w & 3) * 32, wn = (w >> 2) * 32;   // warp tile 32x32
    int R0 = (blockIdx.x >> 1) * 128;
    int N0 = (blockIdx.x & 1) * 64;

    float acc[2][4][4];
    #pragma unroll
    for (int mt = 0; mt < 2; mt++)
        #pragma unroll
        for (int j = 0; j < 4; j++)
            #pragma unroll
            for (int q = 0; q < 4; q++) acc[mt][j][q] = 0.f;

    auto load_chunk = [&](int c) {
        uint32_t stg = sb + (uint32_t)c * 24576u;
        uint32_t aB = stg;
        uint32_t bB = stg + 16384u;
        const uint16_t* A = (c < 2) ? Ahs : Af0;
        const uint16_t* B = (c < 2) ? Bw1 : Bw2;
        int ko = (c & 1) * 64;
        #pragma unroll
        for (int i = 0; i < 4; i++) {        // A: 128 rows x 128B
            int idx = i * 256 + t;
            int r = idx >> 3, f4 = idx & 7;
            int row = R0 + r; if (row >= NN) row = 0;
            uint32_t off = r * 128 + ((f4 * 16) ^ ((r & 7) << 4));
            cpa16(aB + off, A + (size_t)row * DD + ko + f4 * 8);
        }
        #pragma unroll
        for (int i = 0; i < 2; i++) {        // B: 64 rows x 128B
            int idx = i * 256 + t;
            int r = idx >> 3, f4 = idx & 7;
            uint32_t off = r * 128 + ((f4 * 16) ^ ((r & 7) << 4));
            cpa16(bB + off, B + (size_t)(N0 + r) * DD + ko + f4 * 8);
        }
        asm volatile("cp.async.commit_group;" ::: "memory");
    };

    // full prefetch: all DRAM loads of this block in flight at once
    load_chunk(0);
    load_chunk(1);
    load_chunk(2);
    load_chunk(3);

    int rA[2], rB[2];
    #pragma unroll
    for (int mt = 0; mt < 2; mt++)
        rA[mt] = wm + mt * 16 + (lane & 7) + ((lane >> 3) & 1) * 8;
    #pragma unroll
    for (int nt = 0; nt < 2; nt++)
        rB[nt] = wn + nt * 16 + (lane & 7) + ((lane >> 4) & 1) * 8;
    uint32_t aH = ((lane >> 4) & 1) * 16;
    uint32_t bH = ((lane >> 3) & 1) * 16;

    #pragma unroll
    for (int c = 0; c < 4; c++) {
        if (c == 0)      asm volatile("cp.async.wait_group 3;" ::: "memory");
        else if (c == 1) asm volatile("cp.async.wait_group 2;" ::: "memory");
        else if (c == 2) asm volatile("cp.async.wait_group 1;" ::: "memory");
        else             asm volatile("cp.async.wait_group 0;" ::: "memory");
        __syncthreads();

        uint32_t stg = sb + (uint32_t)c * 24576u;
        uint32_t aB = stg;
        uint32_t bB = stg + 16384u;
        #pragma unroll
        for (int kk = 0; kk < 4; kk++) {
            uint32_t a[2][4], b[2][4];
            #pragma unroll
            for (int mt = 0; mt < 2; mt++)
                ldsm4(a[mt], aB + rA[mt] * 128 +
                              (((uint32_t)(kk * 32) + aH) ^ ((rA[mt] & 7) << 4)));
            #pragma unroll
            for (int nt = 0; nt < 2; nt++)
                ldsm4(b[nt], bB + rB[nt] * 128 +
                              (((uint32_t)(kk * 32) + bH) ^ ((rB[nt] & 7) << 4)));
            #pragma unroll
            for (int mt = 0; mt < 2; mt++)
                #pragma unroll
                for (int nt = 0; nt < 2; nt++) {
                    mma16(acc[mt][2 * nt + 0], a[mt], b[nt][0], b[nt][1]);
                    mma16(acc[mt][2 * nt + 1], a[mt], b[nt][2], b[nt][3]);
                }
        }
    }

    if (MODE == 0) {
        // epilogue: bias + relu + norm-prescale + fp8 pack
        #pragma unroll
        for (int mt = 0; mt < 2; mt++) {
            int row0 = R0 + wm + mt * 16 + (lane >> 2);
            float nr0 = (row0 < NN) ? g_norm[row0] : 0.f;
            float nr1 = (row0 + 8 < NN) ? g_norm[row0 + 8] : 0.f;
            #pragma unroll
            for (int j = 0; j < 4; j++) {
                int col = N0 + wn + j * 8 + (lane & 3) * 2;
                float2 bb = *(const float2*)(bias + col);
                float v0 = fmaxf(acc[mt][j][0] + bb.x, 0.f) * nr0;
                float v1 = fmaxf(acc[mt][j][1] + bb.y, 0.f) * nr0;
                float v2 = fmaxf(acc[mt][j][2] + bb.x, 0.f) * nr1;
                float v3 = fmaxf(acc[mt][j][3] + bb.y, 0.f) * nr1;
                if (row0 < NN)
                    *(uint16_t*)(x8out + (size_t)row0 * DD + col) = fp8pack(v0, v1);
                if (row0 + 8 < NN)
                    *(uint16_t*)(x8out + (size_t)(row0 + 8) * DD + col) = fp8pack(v2, v3);
            }
        }
    } else {
        // pooled epilogue: rows r0, r0+8, r0+16, r0+24 per thread
        int r0 = R0 + wm + (lane >> 2);
        int ra = r0, rb = r0 + 8, rc = r0 + 16, rd = r0 + 24;
        bool va = ra < NN, vb = rb < NN, vc = rc < NN, vd = rd < NN;
        if (va) {
            int ga = __ldg(gids + ra);
            int gb = vb ? __ldg(gids + rb) : ga;
            int gc = vc ? __ldg(gids + rc) : ga;
            int gd = vd ? __ldg(gids + rd) : ga;
            bool same = (ga == gb) && (gb == gc) && (gc == gd);
            #pragma unroll
            for (int j = 0; j < 4; j++) {
                int col = N0 + wn + j * 8 + (lane & 3) * 2;
                float2 bb = *(const float2*)(bias + col);
                #pragma unroll
                for (int q = 0; q < 2; q++) {
                    float bq = q ? bb.y : bb.x;
                    float u0 = va ? fmaxf(acc[0][j][q + 0] + bq, 0.f) : 0.f;
                    float u1 = vb ? fmaxf(acc[0][j][q + 2] + bq, 0.f) : 0.f;
                    float u2 = vc ? fmaxf(acc[1][j][q + 0] + bq, 0.f) : 0.f;
                    float u3 = vd ? fmaxf(acc[1][j][q + 2] + bq, 0.f) : 0.f;
                    if (same) {
                        atomicAdd(&g_pooled[ga * DD + col + q], u0 + u1 + u2 + u3);
                    } else {
                        atomicAdd(&g_pooled[ga * DD + col + q], u0);
                        if (vb) atomicAdd(&g_pooled[gb * DD + col + q], u1);
                        if (vc) atomicAdd(&g_pooled[gc * DD + col + q], u2);
                        if (vd) atomicAdd(&g_pooled[gd * DD + col + q], u3);
                    }
                }
            }
        }
    }
}

// ---------------- final MLP ----------------
__global__ void k_mlp(const float* __restrict__ d1w, const float* __restrict__ d1b,
                      const float* __restrict__ d2w, const float* __restrict__ d2b,
                      float* __restrict__ out) {
    int b = threadIdx.x;
    if (b >= NG) return;
    float inv = 1.f / fmaxf((float)g_gcnt[b], 1.f);
    float h[PHH];
    #pragma unroll
    for (int p = 0; p < PHH; p++) h[p] = __ldg(d1b + p);
    for (int c = 0; c < DD; c++) {
        float a = g_pooled[b * DD + c] * inv;
        #pragma unroll
        for (int p = 0; p < PHH; p++)
            h[p] = fmaf(a, __ldg(d1w + c * PHH + p), h[p]);
    }
    float z = __ldg(d2b);
    #pragma unroll
    for (int p = 0; p < PHH; p++)
        z = fmaf(fmaxf(h[p], 0.f), __ldg(d2w + p), z);
    out[b] = 1.f / (1.f + expf(-z));
}

// ---------------- launch ----------------
extern "C" void kernel_launch(void* const* d_in, const int* in_sizes, int n_in,
                              void* d_out, int out_size) {
    const float* feature = (const float*)d_in[0];
    const int*   src     = (const int*)d_in[1];
    const int*   dst     = (const int*)d_in[2];
    const int*   gids    = (const int*)d_in[3];
    const float* w1_1    = (const float*)d_in[4];
    const float* w2_1    = (const float*)d_in[5];
    const float* b_1     = (const float*)d_in[6];
    const float* w1_2    = (const float*)d_in[7];
    const float* w2_2    = (const float*)d_in[8];
    const float* b_2     = (const float*)d_in[9];
    const float* d1w     = (const float*)d_in[10];
    const float* d1b     = (const float*)d_in[11];
    const float* d2w     = (const float*)d_in[12];
    const float* d2b     = (const float*)d_in[13];
    float* out = (float*)d_out;

    uint16_t *fb_p = nullptr, *hb_p = nullptr, *w1b_p = nullptr, *w2b_p = nullptr;
    uint8_t *fs_p = nullptr, *xs_p = nullptr;
    cudaGetSymbolAddress((void**)&fb_p,   g_fb);
    cudaGetSymbolAddress((void**)&fs_p,   g_fs);
    cudaGetSymbolAddress((void**)&xs_p,   g_xs);
    cudaGetSymbolAddress((void**)&hb_p,   g_hb);
    cudaGetSymbolAddress((void**)&w1b_p,  g_w1b);
    cudaGetSymbolAddress((void**)&w2b_p,  g_w2b);

    const int SMEM_MMA = 98304;   // 4 stages x (A 16KB + B 8KB)
    cudaFuncSetAttribute(k_mma<0>, cudaFuncAttributeMaxDynamicSharedMemorySize, SMEM_MMA);
    cudaFuncSetAttribute(k_mma<1>, cudaFuncAttributeMaxDynamicSharedMemorySize, SMEM_MMA);

    k_zero<<<(NN + 255) / 256, 256>>>();
    k_pre<<<(NN * DD / 4 + 255) / 256, 256>>>(feature, dst, w1_1, w2_1, w1_2, w2_2);
    k_scan<<<NSB, 1024>>>(gids);
    k_fill<<<(NN * DD / 4 + 255) / 256, 256>>>(src, dst);

    // layer 1: spmm gathers fp8 norm⊙feature -> hs (bf16);
    //          gemm (hb, fb) -> fp8 norm⊙x1
    k_spmm<<<(NN * 16 + 255) / 256, 256>>>(fs_p, hb_p);
    k_mma<0><<<NTILES * 2, 256, SMEM_MMA>>>(hb_p, fb_p, w1b_p, w2b_p, b_1, xs_p, gids);
    // layer 2: spmm gathers fp8 norm⊙x1 -> hs (bf16);
    //          gemm (hb, fb) pools directly into g_pooled
    k_spmm<<<(NN * 16 + 255) / 256, 256>>>(xs_p, hb_p);
    k_mma<1><<<NTILES * 2, 256, SMEM_MMA>>>(hb_p, fb_p,
                                            w1b_p + DD * DD, w2b_p + DD * DD, b_2,
                                            nullptr, gids);
    // decoder
    k_mlp<<<1, 64>>>(d1w, d1b, d2w, d2b, out);
}

// round 14
// speedup vs baseline: 1.1387x; 1.1387x over previous
#include <cuda_runtime.h>
#include <cuda_bf16.h>
#include <math.h>
#include <stdint.h>

#define NN  100000
#define NE  1600000
#define DD  128
#define NG  64
#define PHH 32
#define NTILES 782   // ceil(NN/128)
#define NSB 98       // scan blocks

// ---------------- device scratch (no allocations allowed) ----------------
// INVARIANT: g_deg, g_fill, g_agg, g_gcnt, g_pooled are all-zero at every
// kernel_launch entry; each is re-zeroed by the kernel after its last reader.
__device__ int      g_deg[NN];
__device__ int      g_off[NN + 1];
__device__ int      g_fill[NN];
__device__ unsigned g_agg[128];            // lookback aggregates (bit31 = valid)
__device__ int      g_csr[NE];
__device__ int      g_gcnt[NG];
__device__ float    g_norm[NN];
__device__ float    g_pooled[NG * DD];
__device__ uint16_t g_fb[NN * DD];         // bf16 feature, unscaled (GEMM f0)
__device__ uint8_t  g_fs[NN * DD];         // fp8 norm⊙feature (L1 gather)
__device__ uint8_t  g_xs[NN * DD];         // fp8 norm⊙x1 (L2 gather)
__device__ uint16_t g_hb[NN * DD];         // bf16 hs (GEMM A operand)
__device__ uint16_t g_w1b[2][DD * DD];     // effective W1 per layer, [n][k], bf16
__device__ uint16_t g_w2b[2][DD * DD];     // effective W2 (x0.5) per layer, bf16

// ---------------- helpers ----------------
__device__ __forceinline__ uint32_t smem_u32(const void* p) {
    uint32_t a;
    asm("{ .reg .u64 t; cvta.to.shared.u64 t, %1; cvt.u32.u64 %0, t; }"
        : "=r"(a) : "l"(p));
    return a;
}

__device__ __forceinline__ uint32_t bf2pack(float lo, float hi) {
    uint32_t p;
    asm("cvt.rn.bf16x2.f32 %0, %1, %2;" : "=r"(p) : "f"(hi), "f"(lo));
    return p;
}

__device__ __forceinline__ uint16_t bf1(float v) {
    return (uint16_t)(bf2pack(v, 0.f) & 0xFFFFu);
}

// pack 2 floats -> e4m3x2 (lo in low byte)
__device__ __forceinline__ uint16_t fp8pack(float lo, float hi) {
    uint16_t r;
    asm("cvt.rn.satfinite.e4m3x2.f32 %0, %1, %2;" : "=h"(r) : "f"(hi), "f"(lo));
    return r;
}

// 4 fp8 (one u32) -> two half2
__device__ __forceinline__ void fp8x4_to_h2x2(uint32_t w, uint32_t& h01, uint32_t& h23) {
    asm("{ .reg .b16 lo, hi;\n\t"
        "mov.b32 {lo, hi}, %2;\n\t"
        "cvt.rn.f16x2.e4m3x2 %0, lo;\n\t"
        "cvt.rn.f16x2.e4m3x2 %1, hi; }"
        : "=r"(h01), "=r"(h23) : "r"(w));
}

__device__ __forceinline__ uint32_t hadd2(uint32_t a, uint32_t b) {
    uint32_t r;
    asm("add.f16x2 %0, %1, %2;" : "=r"(r) : "r"(a), "r"(b));
    return r;
}

__device__ __forceinline__ float2 h2f(uint32_t h) {
    float2 f;
    asm("{ .reg .b16 lo, hi;\n\t"
        "mov.b32 {lo, hi}, %2;\n\t"
        "cvt.f32.f16 %0, lo;\n\t"
        "cvt.f32.f16 %1, hi; }"
        : "=f"(f.x), "=f"(f.y) : "r"(h));
    return f;
}

__device__ __forceinline__ void cpa16(uint32_t dst, const void* src) {
    asm volatile("cp.async.cg.shared.global [%0], [%1], 16;"
                 :: "r"(dst), "l"(src) : "memory");
}

__device__ __forceinline__ void ldsm4(uint32_t* r, uint32_t addr) {
    asm volatile("ldmatrix.sync.aligned.m8n8.x4.shared.b16 {%0,%1,%2,%3}, [%4];"
                 : "=r"(r[0]), "=r"(r[1]), "=r"(r[2]), "=r"(r[3]) : "r"(addr));
}

__device__ __forceinline__ void mma16(float* c, const uint32_t* a,
                                      uint32_t b0, uint32_t b1) {
    asm volatile(
        "mma.sync.aligned.m16n8k16.row.col.f32.bf16.bf16.f32 "
        "{%0,%1,%2,%3}, {%4,%5,%6,%7}, {%8,%9}, {%0,%1,%2,%3};"
        : "+f"(c[0]), "+f"(c[1]), "+f"(c[2]), "+f"(c[3])
        : "r"(a[0]), "r"(a[1]), "r"(a[2]), "r"(a[3]), "r"(b0), "r"(b1));
}

__device__ __forceinline__ float bflo(uint32_t u) { return __uint_as_float(u << 16); }
__device__ __forceinline__ float bfhi(uint32_t u) { return __uint_as_float(u & 0xFFFF0000u); }

// ---------------- setup ----------------
// fused: degree count + bf16 feature copy + effective-weight prep
__global__ void k_pre(const float* __restrict__ feat, const int* __restrict__ dst,
                      const float* __restrict__ w11, const float* __restrict__ w21,
                      const float* __restrict__ w12, const float* __restrict__ w22) {
    int i = blockIdx.x * blockDim.x + threadIdx.x;
    if (i < NE) atomicAdd(&g_deg[dst[i]], 1);
    if (i < NN * DD / 4) {
        float4 v = __ldg((const float4*)feat + i);
        uint2 b;
        b.x = bf2pack(v.x, v.y);
        b.y = bf2pack(v.z, v.w);
        ((uint2*)g_fb)[i] = b;
    }
    if (i < DD * DD) {
        const float B1 = 0.6931471805599453f;  // log 2
        const float B2 = 0.4054651081081644f;  // log 1.5
        int n = i >> 7, k = i & 127;
        float ikn = (k == n) ? 1.f : 0.f;
        g_w1b[0][n * DD + k] = bf1(B1 * w11[k * DD + n] + (1.f - B1) * ikn);
        g_w2b[0][n * DD + k] = bf1(0.5f * (B1 * w21[k * DD + n] + (1.f - B1) * ikn));
        g_w1b[1][n * DD + k] = bf1(B2 * w12[k * DD + n] + (1.f - B2) * ikn);
        g_w2b[1][n * DD + k] = bf1(0.5f * (B2 * w22[k * DD + n] + (1.f - B2) * ikn));
    }
}

// fused scan: warp-shuffle block scan + lookback + norm/gcnt; re-zeros g_deg
__global__ void k_scan(const int* __restrict__ gids) {
    __shared__ int wsum[32];
    __shared__ int blockoff;
    int b = blockIdx.x, t = threadIdx.x;
    int wid = t >> 5, ln = t & 31;
    int i = b * 1024 + t;
    int v = (i < NN) ? g_deg[i] : 0;
    // warp inclusive scan
    int x = v;
    #pragma unroll
    for (int o = 1; o < 32; o <<= 1) {
        int y = __shfl_up_sync(0xFFFFFFFFu, x, o);
        if (ln >= o) x += y;
    }
    if (ln == 31) wsum[wid] = x;
    __syncthreads();
    if (wid == 0) {
        int s = wsum[ln];
        #pragma unroll
        for (int o = 1; o < 32; o <<= 1) {
            int y = __shfl_up_sync(0xFFFFFFFFu, s, o);
            if (ln >= o) s += y;
        }
        wsum[ln] = s;
    }
    __syncthreads();
    int incl = x + (wid ? wsum[wid - 1] : 0);   // block-inclusive scan of v
    if (t == 1023)
        atomicExch(&g_agg[b], 0x80000000u | (unsigned)incl);
    if (t < 32) {
        int sum = 0;
        for (int base = 0; base < b; base += 32) {
            int idx = base + t;
            unsigned val = 0;
            if (idx < b) {
                do { val = *(volatile unsigned*)&g_agg[idx]; }
                while (!(val & 0x80000000u));
            }
            sum += (int)(val & 0x7FFFFFFFu);
        }
        #pragma unroll
        for (int o = 16; o > 0; o >>= 1)
            sum += __shfl_down_sync(0xFFFFFFFFu, sum, o);
        if (t == 0) blockoff = sum;
    }
    __syncthreads();
    if (i < NN) {
        g_off[i] = blockoff + incl - v;
        g_norm[i] = rsqrtf((float)(v + 1));   // +1 self loop
        g_deg[i] = 0;                         // restore zero for next replay
        atomicAdd(&g_gcnt[gids[i]], 1);
    }
    if (i == NN) g_off[NN] = NE;
}

// fused: CSR fill + fp8 scaled feature + g_agg re-zero (scan is complete here)
__global__ void k_fill(const int* __restrict__ src, const int* __restrict__ dst) {
    int i = blockIdx.x * blockDim.x + threadIdx.x;
    if (i < NE) {
        int d = dst[i];
        int p = g_off[d] + atomicAdd(&g_fill[d], 1);
        g_csr[p] = src[i];
    }
    if (i < NN * DD / 4) {
        int node = i >> 5;                  // 32 quads per row
        float nrm = g_norm[node];
        uint2 b = ((const uint2*)g_fb)[i];
        uint16_t p0 = fp8pack(bflo(b.x) * nrm, bfhi(b.x) * nrm);
        uint16_t p1 = fp8pack(bflo(b.y) * nrm, bfhi(b.y) * nrm);
        ((uint32_t*)g_fs)[i] = (uint32_t)p0 | ((uint32_t)p1 << 16);
    }
    if (i < 128) g_agg[i] = 0u;             // restore zero (all scan readers done)
}

// ---- SpMM (fp8 gather, half2 accumulate): hs = bf16(0.5*nrm*(x̃[n]+Σx̃[src]))
// 16-lane node groups (uint2 = 8 fp8/lane), 8-edge unroll. Re-zeros g_fill.
__global__ void k_spmm(const uint8_t* __restrict__ fin, uint16_t* __restrict__ fout) {
    int gt = blockIdx.x * blockDim.x + threadIdx.x;
    int node = gt >> 4, lane = gt & 15;
    if (node >= NN) return;
    if (lane == 0) g_fill[node] = 0;        // restore zero (idempotent on L2 call)
    const uint2* F = (const uint2*)fin;     // row = 128B = 16 x uint2
    uint2 a = __ldg(F + (size_t)node * 16 + lane);   // self loop (pre-scaled)
    uint32_t h[4];
    fp8x4_to_h2x2(a.x, h[0], h[1]);
    fp8x4_to_h2x2(a.y, h[2], h[3]);

    int beg = g_off[node], end = g_off[node + 1];
    int e = beg;
    for (; e + 8 <= end; e += 8) {
        uint2 v[8];
        #pragma unroll
        for (int j = 0; j < 8; j++) {
            int s = __ldg(g_csr + e + j);
            v[j] = __ldg(F + (size_t)s * 16 + lane);
        }
        #pragma unroll
        for (int j = 0; j < 8; j++) {
            uint32_t c0, c1, c2, c3;
            fp8x4_to_h2x2(v[j].x, c0, c1);
            fp8x4_to_h2x2(v[j].y, c2, c3);
            h[0] = hadd2(h[0], c0);
            h[1] = hadd2(h[1], c1);
            h[2] = hadd2(h[2], c2);
            h[3] = hadd2(h[3], c3);
        }
    }
    for (; e < end; e++) {
        int s = __ldg(g_csr + e);
        uint2 v0 = __ldg(F + (size_t)s * 16 + lane);
        uint32_t c0, c1, c2, c3;
        fp8x4_to_h2x2(v0.x, c0, c1);
        fp8x4_to_h2x2(v0.y, c2, c3);
        h[0] = hadd2(h[0], c0);
        h[1] = hadd2(h[1], c1);
        h[2] = hadd2(h[2], c2);
        h[3] = hadd2(h[3], c3);
    }
    float sc = 0.5f * g_norm[node];
    float2 f0 = h2f(h[0]), f1 = h2f(h[1]), f2 = h2f(h[2]), f3 = h2f(h[3]);
    uint4 o;
    o.x = bf2pack(f0.x * sc, f0.y * sc);
    o.y = bf2pack(f1.x * sc, f1.y * sc);
    o.z = bf2pack(f2.x * sc, f2.y * sc);
    o.w = bf2pack(f3.x * sc, f3.y * sc);
    ((uint4*)fout)[(size_t)node * 16 + lane] = o;
}

// ---- bf16 mma.sync GEMM: relu(hs@W1e + f0@W2e + b)  (R9 best config) ------
// BM=128, BN=128, K=256 (hs|f0), BK=64 bf16 (128B rows), 4 chunks,
// 8 warps (warp tile 32x64), 2-stage cp.async pipeline, SW128 swizzle.
// MODE 0: write fp8 norm⊙x1 (feeds L2 gather). MODE 1: pool into g_pooled.
template <int MODE>
__global__ void __launch_bounds__(256, 2)
k_mma(const uint16_t* __restrict__ Ahs, const uint16_t* __restrict__ Af0,
      const uint16_t* __restrict__ Bw1, const uint16_t* __restrict__ Bw2,
      const float* __restrict__ bias, uint8_t* __restrict__ x8out,
      const int* __restrict__ gids) {
    extern __shared__ float smem[];   // 2 stages x (A 16KB + B 16KB)
    uint32_t sb = smem_u32(smem);
    int t = threadIdx.x, lane = t & 31, w = t >> 5;
    int wm = (w & 3) * 32, wn = (w >> 2) * 64;
    int R0 = blockIdx.x * 128;

    float acc[2][8][4];
    #pragma unroll
    for (int mt = 0; mt < 2; mt++)
        #pragma unroll
        for (int j = 0; j < 8; j++)
            #pragma unroll
            for (int q = 0; q < 4; q++) acc[mt][j][q] = 0.f;

    auto load_chunk = [&](int c) {
        int s = c & 1;
        uint32_t aB = sb + s * 32768;
        uint32_t bB = aB + 16384;
        const uint16_t* A = (c < 2) ? Ahs : Af0;
        const uint16_t* B = (c < 2) ? Bw1 : Bw2;
        int ko = (c & 1) * 64;
        #pragma unroll
        for (int i = 0; i < 4; i++) {
            int idx = i * 256 + t;
            int r = idx >> 3, f4 = idx & 7;
            int row = R0 + r; if (row >= NN) row = 0;
            uint32_t off = r * 128 + ((f4 * 16) ^ ((r & 7) << 4));
            cpa16(aB + off, A + (size_t)row * DD + ko + f4 * 8);
            cpa16(bB + off, B + (size_t)r * DD + ko + f4 * 8);
        }
        asm volatile("cp.async.commit_group;" ::: "memory");
    };

    load_chunk(0);
    load_chunk(1);

    int rA[2], rB[4];
    #pragma unroll
    for (int mt = 0; mt < 2; mt++)
        rA[mt] = wm + mt * 16 + (lane & 7) + ((lane >> 3) & 1) * 8;
    #pragma unroll
    for (int nt = 0; nt < 4; nt++)
        rB[nt] = wn + nt * 16 + (lane & 7) + ((lane >> 4) & 1) * 8;
    uint32_t aH = ((lane >> 4) & 1) * 16;
    uint32_t bH = ((lane >> 3) & 1) * 16;

    for (int c = 0; c < 4; c++) {
        int s = c & 1;
        if (c < 3) asm volatile("cp.async.wait_group 1;" ::: "memory");
        else       asm volatile("cp.async.wait_group 0;" ::: "memory");
        __syncthreads();

        uint32_t aB = sb + s * 32768;
        uint32_t bB = aB + 16384;
        #pragma unroll
        for (int kk = 0; kk < 4; kk++) {
            uint32_t a[2][4], b[4][4];
            #pragma unroll
            for (int mt = 0; mt < 2; mt++)
                ldsm4(a[mt], aB + rA[mt] * 128 +
                              (((uint32_t)(kk * 32) + aH) ^ ((rA[mt] & 7) << 4)));
            #pragma unroll
            for (int nt = 0; nt < 4; nt++)
                ldsm4(b[nt], bB + rB[nt] * 128 +
                              (((uint32_t)(kk * 32) + bH) ^ ((rB[nt] & 7) << 4)));
            #pragma unroll
            for (int mt = 0; mt < 2; mt++)
                #pragma unroll
                for (int nt = 0; nt < 4; nt++) {
                    mma16(acc[mt][2 * nt + 0], a[mt], b[nt][0], b[nt][1]);
                    mma16(acc[mt][2 * nt + 1], a[mt], b[nt][2], b[nt][3]);
                }
        }
        __syncthreads();
        if (c + 2 < 4) load_chunk(c + 2);
    }

    if (MODE == 0) {
        // epilogue: bias + relu + norm-prescale + fp8 pack
        #pragma unroll
        for (int mt = 0; mt < 2; mt++) {
            int row0 = R0 + wm + mt * 16 + (lane >> 2);
            float nr0 = (row0 < NN) ? g_norm[row0] : 0.f;
            float nr1 = (row0 + 8 < NN) ? g_norm[row0 + 8] : 0.f;
            #pragma unroll
            for (int j = 0; j < 8; j++) {
                int col = wn + j * 8 + (lane & 3) * 2;
                float2 bb = *(const float2*)(bias + col);
                float v0 = fmaxf(acc[mt][j][0] + bb.x, 0.f) * nr0;
                float v1 = fmaxf(acc[mt][j][1] + bb.y, 0.f) * nr0;
                float v2 = fmaxf(acc[mt][j][2] + bb.x, 0.f) * nr1;
                float v3 = fmaxf(acc[mt][j][3] + bb.y, 0.f) * nr1;
                if (row0 < NN)
                    *(uint16_t*)(x8out + (size_t)row0 * DD + col) = fp8pack(v0, v1);
                if (row0 + 8 < NN)
                    *(uint16_t*)(x8out + (size_t)(row0 + 8) * DD + col) = fp8pack(v2, v3);
            }
        }
    } else {
        // pooled epilogue: rows r0, r0+8, r0+16, r0+24 per thread
        int r0 = R0 + wm + (lane >> 2);
        int ra = r0, rb = r0 + 8, rc = r0 + 16, rd = r0 + 24;
        bool va = ra < NN, vb = rb < NN, vc = rc < NN, vd = rd < NN;
        if (va) {
            int ga = __ldg(gids + ra);
            int gb = vb ? __ldg(gids + rb) : ga;
            int gc = vc ? __ldg(gids + rc) : ga;
            int gd = vd ? __ldg(gids + rd) : ga;
            bool same = (ga == gb) && (gb == gc) && (gc == gd);
            #pragma unroll
            for (int j = 0; j < 8; j++) {
                int col = wn + j * 8 + (lane & 3) * 2;
                float2 bb = *(const float2*)(bias + col);
                #pragma unroll
                for (int q = 0; q < 2; q++) {
                    float bq = q ? bb.y : bb.x;
                    float u0 = va ? fmaxf(acc[0][j][q + 0] + bq, 0.f) : 0.f;
                    float u1 = vb ? fmaxf(acc[0][j][q + 2] + bq, 0.f) : 0.f;
                    float u2 = vc ? fmaxf(acc[1][j][q + 0] + bq, 0.f) : 0.f;
                    float u3 = vd ? fmaxf(acc[1][j][q + 2] + bq, 0.f) : 0.f;
                    if (same) {
                        atomicAdd(&g_pooled[ga * DD + col + q], u0 + u1 + u2 + u3);
                    } else {
                        atomicAdd(&g_pooled[ga * DD + col + q], u0);
                        if (vb) atomicAdd(&g_pooled[gb * DD + col + q], u1);
                        if (vc) atomicAdd(&g_pooled[gc * DD + col + q], u2);
                        if (vd) atomicAdd(&g_pooled[gd * DD + col + q], u3);
                    }
                }
            }
        }
    }
}

// ---------------- final MLP (re-zeros g_pooled / g_gcnt after use) ---------
__global__ void k_mlp(const float* __restrict__ d1w, const float* __restrict__ d1b,
                      const float* __restrict__ d2w, const float* __restrict__ d2b,
                      float* __restrict__ out) {
    int b = threadIdx.x;
    if (b >= NG) return;
    float inv = 1.f / fmaxf((float)g_gcnt[b], 1.f);
    float h[PHH];
    #pragma unroll
    for (int p = 0; p < PHH; p++) h[p] = __ldg(d1b + p);
    for (int c = 0; c < DD; c++) {
        float a = g_pooled[b * DD + c] * inv;
        g_pooled[b * DD + c] = 0.f;          // restore zero for next replay
        #pragma unroll
        for (int p = 0; p < PHH; p++)
            h[p] = fmaf(a, __ldg(d1w + c * PHH + p), h[p]);
    }
    g_gcnt[b] = 0;                           // restore zero
    float z = __ldg(d2b);
    #pragma unroll
    for (int p = 0; p < PHH; p++)
        z = fmaf(fmaxf(h[p], 0.f), __ldg(d2w + p), z);
    out[b] = 1.f / (1.f + expf(-z));
}

// ---------------- launch ----------------
extern "C" void kernel_launch(void* const* d_in, const int* in_sizes, int n_in,
                              void* d_out, int out_size) {
    const float* feature = (const float*)d_in[0];
    const int*   src     = (const int*)d_in[1];
    const int*   dst     = (const int*)d_in[2];
    const int*   gids    = (const int*)d_in[3];
    const float* w1_1    = (const float*)d_in[4];
    const float* w2_1    = (const float*)d_in[5];
    const float* b_1     = (const float*)d_in[6];
    const float* w1_2    = (const float*)d_in[7];
    const float* w2_2    = (const float*)d_in[8];
    const float* b_2     = (const float*)d_in[9];
    const float* d1w     = (const float*)d_in[10];
    const float* d1b     = (const float*)d_in[11];
    const float* d2w     = (const float*)d_in[12];
    const float* d2b     = (const float*)d_in[13];
    float* out = (float*)d_out;

    uint16_t *fb_p = nullptr, *hb_p = nullptr, *w1b_p = nullptr, *w2b_p = nullptr;
    uint8_t *fs_p = nullptr, *xs_p = nullptr;
    cudaGetSymbolAddress((void**)&fb_p,   g_fb);
    cudaGetSymbolAddress((void**)&fs_p,   g_fs);
    cudaGetSymbolAddress((void**)&xs_p,   g_xs);
    cudaGetSymbolAddress((void**)&hb_p,   g_hb);
    cudaGetSymbolAddress((void**)&w1b_p,  g_w1b);
    cudaGetSymbolAddress((void**)&w2b_p,  g_w2b);

    const int SMEM_MMA = 65536;   // 2 stages x (A 16KB + B 16KB)
    cudaFuncSetAttribute(k_mma<0>, cudaFuncAttributeMaxDynamicSharedMemorySize, SMEM_MMA);
    cudaFuncSetAttribute(k_mma<1>, cudaFuncAttributeMaxDynamicSharedMemorySize, SMEM_MMA);

    k_pre<<<(NN * DD / 4 + 255) / 256, 256>>>(feature, dst, w1_1, w2_1, w1_2, w2_2);
    k_scan<<<NSB, 1024>>>(gids);
    k_fill<<<(NN * DD / 4 + 255) / 256, 256>>>(src, dst);

    // layer 1: spmm gathers fp8 norm⊙feature -> hs (bf16);
    //          gemm (hb, fb) -> fp8 norm⊙x1
    k_spmm<<<(NN * 16 + 255) / 256, 256>>>(fs_p, hb_p);
    k_mma<0><<<NTILES, 256, SMEM_MMA>>>(hb_p, fb_p, w1b_p, w2b_p, b_1, xs_p, gids);
    // layer 2: spmm gathers fp8 norm⊙x1 -> hs (bf16);
    //          gemm (hb, fb) pools directly into g_pooled
    k_spmm<<<(NN * 16 + 255) / 256, 256>>>(xs_p, hb_p);
    k_mma<1><<<NTILES, 256, SMEM_MMA>>>(hb_p, fb_p,
                                        w1b_p + DD * DD, w2b_p + DD * DD, b_2,
                                        nullptr, gids);
    // decoder
    k_mlp<<<1, 64>>>(d1w, d1b, d2w, d2b, out);
}

// round 15
// speedup vs baseline: 1.1893x; 1.0445x over previous
#include <cuda_runtime.h>
#include <cuda_bf16.h>
#include <math.h>
#include <stdint.h>

#define NN  100000
#define NE  1600000
#define DD  128
#define NG  64
#define PHH 32
#define NTILES 782   // ceil(NN/128)
#define NSB 98       // scan blocks

// ---------------- device scratch (no allocations allowed) ----------------
// INVARIANT: g_deg, g_fill, g_agg, g_gcnt, g_pooled, g_ctr are all-zero at
// every kernel_launch entry; each is re-zeroed after its last reader.
__device__ int      g_deg[NN];
__device__ int      g_off[NN + 1];
__device__ int      g_fill[NN];
__device__ unsigned g_agg[128];            // lookback aggregates (bit31 = valid)
__device__ int      g_csr[NE];
__device__ int      g_gcnt[NG];
__device__ int      g_ctr;                 // last-block-done counter (mma<1>)
__device__ float    g_norm[NN];
__device__ float    g_pooled[NG * DD];
__device__ uint16_t g_fb[NN * DD];         // bf16 feature, unscaled (GEMM f0)
__device__ uint8_t  g_fs[NN * DD];         // fp8 norm⊙feature (L1 gather)
__device__ uint8_t  g_xs[NN * DD];         // fp8 norm⊙x1 (L2 gather)
__device__ uint16_t g_hb[NN * DD];         // bf16 hs (GEMM A operand)
__device__ uint16_t g_w1b[2][DD * DD];     // effective W1 per layer, [n][k], bf16
__device__ uint16_t g_w2b[2][DD * DD];     // effective W2 (x0.5) per layer, bf16

// ---------------- helpers ----------------
__device__ __forceinline__ uint32_t smem_u32(const void* p) {
    uint32_t a;
    asm("{ .reg .u64 t; cvta.to.shared.u64 t, %1; cvt.u32.u64 %0, t; }"
        : "=r"(a) : "l"(p));
    return a;
}

__device__ __forceinline__ uint32_t bf2pack(float lo, float hi) {
    uint32_t p;
    asm("cvt.rn.bf16x2.f32 %0, %1, %2;" : "=r"(p) : "f"(hi), "f"(lo));
    return p;
}

__device__ __forceinline__ uint16_t bf1(float v) {
    return (uint16_t)(bf2pack(v, 0.f) & 0xFFFFu);
}

// pack 2 floats -> e4m3x2 (lo in low byte)
__device__ __forceinline__ uint16_t fp8pack(float lo, float hi) {
    uint16_t r;
    asm("cvt.rn.satfinite.e4m3x2.f32 %0, %1, %2;" : "=h"(r) : "f"(hi), "f"(lo));
    return r;
}

// 4 fp8 (one u32) -> two half2
__device__ __forceinline__ void fp8x4_to_h2x2(uint32_t w, uint32_t& h01, uint32_t& h23) {
    asm("{ .reg .b16 lo, hi;\n\t"
        "mov.b32 {lo, hi}, %2;\n\t"
        "cvt.rn.f16x2.e4m3x2 %0, lo;\n\t"
        "cvt.rn.f16x2.e4m3x2 %1, hi; }"
        : "=r"(h01), "=r"(h23) : "r"(w));
}

__device__ __forceinline__ uint32_t hadd2(uint32_t a, uint32_t b) {
    uint32_t r;
    asm("add.f16x2 %0, %1, %2;" : "=r"(r) : "r"(a), "r"(b));
    return r;
}

__device__ __forceinline__ float2 h2f(uint32_t h) {
    float2 f;
    asm("{ .reg .b16 lo, hi;\n\t"
        "mov.b32 {lo, hi}, %2;\n\t"
        "cvt.f32.f16 %0, lo;\n\t"
        "cvt.f32.f16 %1, hi; }"
        : "=f"(f.x), "=f"(f.y) : "r"(h));
    return f;
}

__device__ __forceinline__ void cpa16(uint32_t dst, const void* src) {
    asm volatile("cp.async.cg.shared.global [%0], [%1], 16;"
                 :: "r"(dst), "l"(src) : "memory");
}

__device__ __forceinline__ void ldsm4(uint32_t* r, uint32_t addr) {
    asm volatile("ldmatrix.sync.aligned.m8n8.x4.shared.b16 {%0,%1,%2,%3}, [%4];"
                 : "=r"(r[0]), "=r"(r[1]), "=r"(r[2]), "=r"(r[3]) : "r"(addr));
}

__device__ __forceinline__ void mma16(float* c, const uint32_t* a,
                                      uint32_t b0, uint32_t b1) {
    asm volatile(
        "mma.sync.aligned.m16n8k16.row.col.f32.bf16.bf16.f32 "
        "{%0,%1,%2,%3}, {%4,%5,%6,%7}, {%8,%9}, {%0,%1,%2,%3};"
        : "+f"(c[0]), "+f"(c[1]), "+f"(c[2]), "+f"(c[3])
        : "r"(a[0]), "r"(a[1]), "r"(a[2]), "r"(a[3]), "r"(b0), "r"(b1));
}

__device__ __forceinline__ float bflo(uint32_t u) { return __uint_as_float(u << 16); }
__device__ __forceinline__ float bfhi(uint32_t u) { return __uint_as_float(u & 0xFFFF0000u); }

// ---------------- setup ----------------
// fused: degree count + bf16 feature copy + effective-weight prep
__global__ void k_pre(const float* __restrict__ feat, const int* __restrict__ dst,
                      const float* __restrict__ w11, const float* __restrict__ w21,
                      const float* __restrict__ w12, const float* __restrict__ w22) {
    int i = blockIdx.x * blockDim.x + threadIdx.x;
    if (i < NE) atomicAdd(&g_deg[dst[i]], 1);
    if (i < NN * DD / 4) {
        float4 v = __ldg((const float4*)feat + i);
        uint2 b;
        b.x = bf2pack(v.x, v.y);
        b.y = bf2pack(v.z, v.w);
        ((uint2*)g_fb)[i] = b;
    }
    if (i < DD * DD) {
        const float B1 = 0.6931471805599453f;  // log 2
        const float B2 = 0.4054651081081644f;  // log 1.5
        int n = i >> 7, k = i & 127;
        float ikn = (k == n) ? 1.f : 0.f;
        g_w1b[0][n * DD + k] = bf1(B1 * w11[k * DD + n] + (1.f - B1) * ikn);
        g_w2b[0][n * DD + k] = bf1(0.5f * (B1 * w21[k * DD + n] + (1.f - B1) * ikn));
        g_w1b[1][n * DD + k] = bf1(B2 * w12[k * DD + n] + (1.f - B2) * ikn);
        g_w2b[1][n * DD + k] = bf1(0.5f * (B2 * w22[k * DD + n] + (1.f - B2) * ikn));
    }
}

// fused scan: warp-shuffle block scan + lookback + norm/gcnt; re-zeros g_deg
__global__ void k_scan(const int* __restrict__ gids) {
    __shared__ int wsum[32];
    __shared__ int blockoff;
    int b = blockIdx.x, t = threadIdx.x;
    int wid = t >> 5, ln = t & 31;
    int i = b * 1024 + t;
    int v = (i < NN) ? g_deg[i] : 0;
    // warp inclusive scan
    int x = v;
    #pragma unroll
    for (int o = 1; o < 32; o <<= 1) {
        int y = __shfl_up_sync(0xFFFFFFFFu, x, o);
        if (ln >= o) x += y;
    }
    if (ln == 31) wsum[wid] = x;
    __syncthreads();
    if (wid == 0) {
        int s = wsum[ln];
        #pragma unroll
        for (int o = 1; o < 32; o <<= 1) {
            int y = __shfl_up_sync(0xFFFFFFFFu, s, o);
            if (ln >= o) s += y;
        }
        wsum[ln] = s;
    }
    __syncthreads();
    int incl = x + (wid ? wsum[wid - 1] : 0);   // block-inclusive scan of v
    if (t == 1023)
        atomicExch(&g_agg[b], 0x80000000u | (unsigned)incl);
    if (t < 32) {
        int sum = 0;
        for (int base = 0; base < b; base += 32) {
            int idx = base + t;
            unsigned val = 0;
            if (idx < b) {
                do { val = *(volatile unsigned*)&g_agg[idx]; }
                while (!(val & 0x80000000u));
            }
            sum += (int)(val & 0x7FFFFFFFu);
        }
        #pragma unroll
        for (int o = 16; o > 0; o >>= 1)
            sum += __shfl_down_sync(0xFFFFFFFFu, sum, o);
        if (t == 0) blockoff = sum;
    }
    __syncthreads();
    if (i < NN) {
        g_off[i] = blockoff + incl - v;
        g_norm[i] = rsqrtf((float)(v + 1));   // +1 self loop
        g_deg[i] = 0;                         // restore zero for next replay
        atomicAdd(&g_gcnt[gids[i]], 1);
    }
    if (i == NN) g_off[NN] = NE;
}

// fused: CSR fill + fp8 scaled feature + g_agg re-zero (scan is complete here)
__global__ void k_fill(const int* __restrict__ src, const int* __restrict__ dst) {
    int i = blockIdx.x * blockDim.x + threadIdx.x;
    if (i < NE) {
        int d = dst[i];
        int p = g_off[d] + atomicAdd(&g_fill[d], 1);
        g_csr[p] = src[i];
    }
    if (i < NN * DD / 4) {
        int node = i >> 5;                  // 32 quads per row
        float nrm = g_norm[node];
        uint2 b = ((const uint2*)g_fb)[i];
        uint16_t p0 = fp8pack(bflo(b.x) * nrm, bfhi(b.x) * nrm);
        uint16_t p1 = fp8pack(bflo(b.y) * nrm, bfhi(b.y) * nrm);
        ((uint32_t*)g_fs)[i] = (uint32_t)p0 | ((uint32_t)p1 << 16);
    }
    if (i < 128) g_agg[i] = 0u;             // restore zero (all scan readers done)
}

// ---- SpMM (fp8 gather, half2 accumulate): hs = bf16(0.5*nrm*(x̃[n]+Σx̃[src]))
// 16-lane node groups (uint2 = 8 fp8/lane), 8-edge unroll. Re-zeros g_fill.
__global__ void k_spmm(const uint8_t* __restrict__ fin, uint16_t* __restrict__ fout) {
    int gt = blockIdx.x * blockDim.x + threadIdx.x;
    int node = gt >> 4, lane = gt & 15;
    if (node >= NN) return;
    if (lane == 0) g_fill[node] = 0;        // restore zero (idempotent on L2 call)
    const uint2* F = (const uint2*)fin;     // row = 128B = 16 x uint2
    uint2 a = __ldg(F + (size_t)node * 16 + lane);   // self loop (pre-scaled)
    uint32_t h[4];
    fp8x4_to_h2x2(a.x, h[0], h[1]);
    fp8x4_to_h2x2(a.y, h[2], h[3]);

    int beg = g_off[node], end = g_off[node + 1];
    int e = beg;
    for (; e + 8 <= end; e += 8) {
        uint2 v[8];
        #pragma unroll
        for (int j = 0; j < 8; j++) {
            int s = __ldg(g_csr + e + j);
            v[j] = __ldg(F + (size_t)s * 16 + lane);
        }
        #pragma unroll
        for (int j = 0; j < 8; j++) {
            uint32_t c0, c1, c2, c3;
            fp8x4_to_h2x2(v[j].x, c0, c1);
            fp8x4_to_h2x2(v[j].y, c2, c3);
            h[0] = hadd2(h[0], c0);
            h[1] = hadd2(h[1], c1);
            h[2] = hadd2(h[2], c2);
            h[3] = hadd2(h[3], c3);
        }
    }
    for (; e < end; e++) {
        int s = __ldg(g_csr + e);
        uint2 v0 = __ldg(F + (size_t)s * 16 + lane);
        uint32_t c0, c1, c2, c3;
        fp8x4_to_h2x2(v0.x, c0, c1);
        fp8x4_to_h2x2(v0.y, c2, c3);
        h[0] = hadd2(h[0], c0);
        h[1] = hadd2(h[1], c1);
        h[2] = hadd2(h[2], c2);
        h[3] = hadd2(h[3], c3);
    }
    float sc = 0.5f * g_norm[node];
    float2 f0 = h2f(h[0]), f1 = h2f(h[1]), f2 = h2f(h[2]), f3 = h2f(h[3]);
    uint4 o;
    o.x = bf2pack(f0.x * sc, f0.y * sc);
    o.y = bf2pack(f1.x * sc, f1.y * sc);
    o.z = bf2pack(f2.x * sc, f2.y * sc);
    o.w = bf2pack(f3.x * sc, f3.y * sc);
    ((uint4*)fout)[(size_t)node * 16 + lane] = o;
}

// ---- bf16 mma.sync GEMM: relu(hs@W1e + f0@W2e + b)  (R9 best config) ------
// BM=128, BN=128, K=256 (hs|f0), BK=64 bf16 (128B rows), 4 chunks,
// 8 warps (warp tile 32x64), 2-stage cp.async pipeline, SW128 swizzle.
// MODE 0: write fp8 norm⊙x1 (feeds L2 gather).
// MODE 1: pool into g_pooled; LAST BLOCK runs the decoder MLP inline.
template <int MODE>
__global__ void __launch_bounds__(256, 2)
k_mma(const uint16_t* __restrict__ Ahs, const uint16_t* __restrict__ Af0,
      const uint16_t* __restrict__ Bw1, const uint16_t* __restrict__ Bw2,
      const float* __restrict__ bias, uint8_t* __restrict__ x8out,
      const int* __restrict__ gids,
      const float* __restrict__ d1w, const float* __restrict__ d1b,
      const float* __restrict__ d2w, const float* __restrict__ d2b,
      float* __restrict__ out) {
    extern __shared__ float smem[];   // 2 stages x (A 16KB + B 16KB)
    uint32_t sb = smem_u32(smem);
    int t = threadIdx.x, lane = t & 31, w = t >> 5;
    int wm = (w & 3) * 32, wn = (w >> 2) * 64;
    int R0 = blockIdx.x * 128;

    float acc[2][8][4];
    #pragma unroll
    for (int mt = 0; mt < 2; mt++)
        #pragma unroll
        for (int j = 0; j < 8; j++)
            #pragma unroll
            for (int q = 0; q < 4; q++) acc[mt][j][q] = 0.f;

    auto load_chunk = [&](int c) {
        int s = c & 1;
        uint32_t aB = sb + s * 32768;
        uint32_t bB = aB + 16384;
        const uint16_t* A = (c < 2) ? Ahs : Af0;
        const uint16_t* B = (c < 2) ? Bw1 : Bw2;
        int ko = (c & 1) * 64;
        #pragma unroll
        for (int i = 0; i < 4; i++) {
            int idx = i * 256 + t;
            int r = idx >> 3, f4 = idx & 7;
            int row = R0 + r; if (row >= NN) row = 0;
            uint32_t off = r * 128 + ((f4 * 16) ^ ((r & 7) << 4));
            cpa16(aB + off, A + (size_t)row * DD + ko + f4 * 8);
            cpa16(bB + off, B + (size_t)r * DD + ko + f4 * 8);
        }
        asm volatile("cp.async.commit_group;" ::: "memory");
    };

    load_chunk(0);
    load_chunk(1);

    int rA[2], rB[4];
    #pragma unroll
    for (int mt = 0; mt < 2; mt++)
        rA[mt] = wm + mt * 16 + (lane & 7) + ((lane >> 3) & 1) * 8;
    #pragma unroll
    for (int nt = 0; nt < 4; nt++)
        rB[nt] = wn + nt * 16 + (lane & 7) + ((lane >> 4) & 1) * 8;
    uint32_t aH = ((lane >> 4) & 1) * 16;
    uint32_t bH = ((lane >> 3) & 1) * 16;

    for (int c = 0; c < 4; c++) {
        int s = c & 1;
        if (c < 3) asm volatile("cp.async.wait_group 1;" ::: "memory");
        else       asm volatile("cp.async.wait_group 0;" ::: "memory");
        __syncthreads();

        uint32_t aB = sb + s * 32768;
        uint32_t bB = aB + 16384;
        #pragma unroll
        for (int kk = 0; kk < 4; kk++) {
            uint32_t a[2][4], b[4][4];
            #pragma unroll
            for (int mt = 0; mt < 2; mt++)
                ldsm4(a[mt], aB + rA[mt] * 128 +
                              (((uint32_t)(kk * 32) + aH) ^ ((rA[mt] & 7) << 4)));
            #pragma unroll
            for (int nt = 0; nt < 4; nt++)
                ldsm4(b[nt], bB + rB[nt] * 128 +
                              (((uint32_t)(kk * 32) + bH) ^ ((rB[nt] & 7) << 4)));
            #pragma unroll
            for (int mt = 0; mt < 2; mt++)
                #pragma unroll
                for (int nt = 0; nt < 4; nt++) {
                    mma16(acc[mt][2 * nt + 0], a[mt], b[nt][0], b[nt][1]);
                    mma16(acc[mt][2 * nt + 1], a[mt], b[nt][2], b[nt][3]);
                }
        }
        __syncthreads();
        if (c + 2 < 4) load_chunk(c + 2);
    }

    if (MODE == 0) {
        // epilogue: bias + relu + norm-prescale + fp8 pack
        #pragma unroll
        for (int mt = 0; mt < 2; mt++) {
            int row0 = R0 + wm + mt * 16 + (lane >> 2);
            float nr0 = (row0 < NN) ? g_norm[row0] : 0.f;
            float nr1 = (row0 + 8 < NN) ? g_norm[row0 + 8] : 0.f;
            #pragma unroll
            for (int j = 0; j < 8; j++) {
                int col = wn + j * 8 + (lane & 3) * 2;
                float2 bb = *(const float2*)(bias + col);
                float v0 = fmaxf(acc[mt][j][0] + bb.x, 0.f) * nr0;
                float v1 = fmaxf(acc[mt][j][1] + bb.y, 0.f) * nr0;
                float v2 = fmaxf(acc[mt][j][2] + bb.x, 0.f) * nr1;
                float v3 = fmaxf(acc[mt][j][3] + bb.y, 0.f) * nr1;
                if (row0 < NN)
                    *(uint16_t*)(x8out + (size_t)row0 * DD + col) = fp8pack(v0, v1);
                if (row0 + 8 < NN)
                    *(uint16_t*)(x8out + (size_t)(row0 + 8) * DD + col) = fp8pack(v2, v3);
            }
        }
    } else {
        // pooled epilogue: rows r0, r0+8, r0+16, r0+24 per thread
        int r0 = R0 + wm + (lane >> 2);
        int ra = r0, rb = r0 + 8, rc = r0 + 16, rd = r0 + 24;
        bool va = ra < NN, vb = rb < NN, vc = rc < NN, vd = rd < NN;
        if (va) {
            int ga = __ldg(gids + ra);
            int gb = vb ? __ldg(gids + rb) : ga;
            int gc = vc ? __ldg(gids + rc) : ga;
            int gd = vd ? __ldg(gids + rd) : ga;
            bool same = (ga == gb) && (gb == gc) && (gc == gd);
            #pragma unroll
            for (int j = 0; j < 8; j++) {
                int col = wn + j * 8 + (lane & 3) * 2;
                float2 bb = *(const float2*)(bias + col);
                #pragma unroll
                for (int q = 0; q < 2; q++) {
                    float bq = q ? bb.y : bb.x;
                    float u0 = va ? fmaxf(acc[0][j][q + 0] + bq, 0.f) : 0.f;
                    float u1 = vb ? fmaxf(acc[0][j][q + 2] + bq, 0.f) : 0.f;
                    float u2 = vc ? fmaxf(acc[1][j][q + 0] + bq, 0.f) : 0.f;
                    float u3 = vd ? fmaxf(acc[1][j][q + 2] + bq, 0.f) : 0.f;
                    if (same) {
                        atomicAdd(&g_pooled[ga * DD + col + q], u0 + u1 + u2 + u3);
                    } else {
                        atomicAdd(&g_pooled[ga * DD + col + q], u0);
                        if (vb) atomicAdd(&g_pooled[gb * DD + col + q], u1);
                        if (vc) atomicAdd(&g_pooled[gc * DD + col + q], u2);
                        if (vd) atomicAdd(&g_pooled[gd * DD + col + q], u3);
                    }
                }
            }
        }

        // ---- last-block-done: run the decoder MLP inline ----
        __shared__ int is_last;
        __threadfence();
        __syncthreads();
        if (t == 0) {
            int v = atomicAdd(&g_ctr, 1);
            is_last = (v == NTILES - 1);
            if (is_last) g_ctr = 0;          // restore zero for next replay
        }
        __syncthreads();
        if (is_last) {
            __threadfence();                 // see all blocks' pooled atomics
            int b = t;
            if (b < NG) {
                float inv = 1.f / fmaxf((float)g_gcnt[b], 1.f);
                float h[PHH];
                #pragma unroll
                for (int p = 0; p < PHH; p++) h[p] = __ldg(d1b + p);
                for (int c2 = 0; c2 < DD; c2++) {
                    float a2 = g_pooled[b * DD + c2] * inv;
                    g_pooled[b * DD + c2] = 0.f;   // restore zero
                    #pragma unroll
                    for (int p = 0; p < PHH; p++)
                        h[p] = fmaf(a2, __ldg(d1w + c2 * PHH + p), h[p]);
                }
                g_gcnt[b] = 0;                     // restore zero
                float z = __ldg(d2b);
                #pragma unroll
                for (int p = 0; p < PHH; p++)
                    z = fmaf(fmaxf(h[p], 0.f), __ldg(d2w + p), z);
                out[b] = 1.f / (1.f + expf(-z));
            }
        }
    }
}

// ---------------- launch ----------------
extern "C" void kernel_launch(void* const* d_in, const int* in_sizes, int n_in,
                              void* d_out, int out_size) {
    const float* feature = (const float*)d_in[0];
    const int*   src     = (const int*)d_in[1];
    const int*   dst     = (const int*)d_in[2];
    const int*   gids    = (const int*)d_in[3];
    const float* w1_1    = (const float*)d_in[4];
    const float* w2_1    = (const float*)d_in[5];
    const float* b_1     = (const float*)d_in[6];
    const float* w1_2    = (const float*)d_in[7];
    const float* w2_2    = (const float*)d_in[8];
    const float* b_2     = (const float*)d_in[9];
    const float* d1w     = (const float*)d_in[10];
    const float* d1b     = (const float*)d_in[11];
    const float* d2w     = (const float*)d_in[12];
    const float* d2b     = (const float*)d_in[13];
    float* out = (float*)d_out;

    uint16_t *fb_p = nullptr, *hb_p = nullptr, *w1b_p = nullptr, *w2b_p = nullptr;
    uint8_t *fs_p = nullptr, *xs_p = nullptr;
    cudaGetSymbolAddress((void**)&fb_p,   g_fb);
    cudaGetSymbolAddress((void**)&fs_p,   g_fs);
    cudaGetSymbolAddress((void**)&xs_p,   g_xs);
    cudaGetSymbolAddress((void**)&hb_p,   g_hb);
    cudaGetSymbolAddress((void**)&w1b_p,  g_w1b);
    cudaGetSymbolAddress((void**)&w2b_p,  g_w2b);

    const int SMEM_MMA = 65536;   // 2 stages x (A 16KB + B 16KB)
    cudaFuncSetAttribute(k_mma<0>, cudaFuncAttributeMaxDynamicSharedMemorySize, SMEM_MMA);
    cudaFuncSetAttribute(k_mma<1>, cudaFuncAttributeMaxDynamicSharedMemorySize, SMEM_MMA);

    k_pre<<<(NN * DD / 4 + 255) / 256, 256>>>(feature, dst, w1_1, w2_1, w1_2, w2_2);
    k_scan<<<NSB, 1024>>>(gids);
    k_fill<<<(NN * DD / 4 + 255) / 256, 256>>>(src, dst);

    // layer 1: spmm gathers fp8 norm⊙feature -> hs (bf16);
    //          gemm (hb, fb) -> fp8 norm⊙x1
    k_spmm<<<(NN * 16 + 255) / 256, 256>>>(fs_p, hb_p);
    k_mma<0><<<NTILES, 256, SMEM_MMA>>>(hb_p, fb_p, w1b_p, w2b_p, b_1, xs_p, gids,
                                        nullptr, nullptr, nullptr, nullptr, nullptr);
    // layer 2: spmm gathers fp8 norm⊙x1 -> hs (bf16);
    //          gemm (hb, fb) pools into g_pooled; last block runs decoder MLP
    k_spmm<<<(NN * 16 + 255) / 256, 256>>>(xs_p, hb_p);
    k_mma<1><<<NTILES, 256, SMEM_MMA>>>(hb_p, fb_p,
                                        w1b_p + DD * DD, w2b_p + DD * DD, b_2,
                                        nullptr, gids, d1w, d1b, d2w, d2b, out);
}

// round 16
// speedup vs baseline: 1.2151x; 1.0217x over previous
#include <cuda_runtime.h>
#include <cuda_bf16.h>
#include <math.h>
#include <stdint.h>

#define NN  100000
#define NE  1600000
#define DD  128
#define NG  64
#define PHH 32
#define NTILES 782   // ceil(NN/128)
#define NSB 98       // scan blocks

// ---------------- device scratch (no allocations allowed) ----------------
// INVARIANT: g_deg, g_fill, g_agg, g_gcnt, g_pooled, g_ctr are all-zero at
// every kernel_launch entry; each is re-zeroed after its last reader.
__device__ int      g_deg[NN];
__device__ int      g_off[NN + 1];
__device__ int      g_fill[NN];
__device__ unsigned g_agg[128];            // lookback aggregates (bit31 = valid)
__device__ int      g_csr[NE];
__device__ int      g_gcnt[NG];
__device__ int      g_ctr;                 // last-block-done counter (mma<1>)
__device__ float    g_norm[NN];
__device__ float    g_pooled[NG * DD];
__device__ uint8_t  g_f8[NN * DD];         // fp8 feature, unscaled (GEMM f0)
__device__ uint8_t  g_fs[NN * DD];         // fp8 norm⊙feature (L1 gather)
__device__ uint8_t  g_xs[NN * DD];         // fp8 norm⊙x1 (L2 gather)
__device__ uint8_t  g_h8[NN * DD];         // fp8 hs (GEMM A operand)
__device__ uint8_t  g_w1q[2][DD * DD];     // effective W1 per layer, [n][k], fp8
__device__ uint8_t  g_w2q[2][DD * DD];     // effective W2 (x0.5) per layer, fp8

// ---------------- helpers ----------------
__device__ __forceinline__ uint32_t smem_u32(const void* p) {
    uint32_t a;
    asm("{ .reg .u64 t; cvta.to.shared.u64 t, %1; cvt.u32.u64 %0, t; }"
        : "=r"(a) : "l"(p));
    return a;
}

// pack 2 floats -> e4m3x2 (lo in low byte)
__device__ __forceinline__ uint16_t fp8pack(float lo, float hi) {
    uint16_t r;
    asm("cvt.rn.satfinite.e4m3x2.f32 %0, %1, %2;" : "=h"(r) : "f"(hi), "f"(lo));
    return r;
}

__device__ __forceinline__ uint8_t fp8one(float v) {
    return (uint8_t)(fp8pack(v, 0.f) & 0xFFu);
}

// 4 fp8 (one u32) -> two half2
__device__ __forceinline__ void fp8x4_to_h2x2(uint32_t w, uint32_t& h01, uint32_t& h23) {
    asm("{ .reg .b16 lo, hi;\n\t"
        "mov.b32 {lo, hi}, %2;\n\t"
        "cvt.rn.f16x2.e4m3x2 %0, lo;\n\t"
        "cvt.rn.f16x2.e4m3x2 %1, hi; }"
        : "=r"(h01), "=r"(h23) : "r"(w));
}

__device__ __forceinline__ uint32_t hadd2(uint32_t a, uint32_t b) {
    uint32_t r;
    asm("add.f16x2 %0, %1, %2;" : "=r"(r) : "r"(a), "r"(b));
    return r;
}

__device__ __forceinline__ float2 h2f(uint32_t h) {
    float2 f;
    asm("{ .reg .b16 lo, hi;\n\t"
        "mov.b32 {lo, hi}, %2;\n\t"
        "cvt.f32.f16 %0, lo;\n\t"
        "cvt.f32.f16 %1, hi; }"
        : "=f"(f.x), "=f"(f.y) : "r"(h));
    return f;
}

__device__ __forceinline__ void cpa16(uint32_t dst, const void* src) {
    asm volatile("cp.async.cg.shared.global [%0], [%1], 16;"
                 :: "r"(dst), "l"(src) : "memory");
}

__device__ __forceinline__ void ldsm4(uint32_t* r, uint32_t addr) {
    asm volatile("ldmatrix.sync.aligned.m8n8.x4.shared.b16 {%0,%1,%2,%3}, [%4];"
                 : "=r"(r[0]), "=r"(r[1]), "=r"(r[2]), "=r"(r[3]) : "r"(addr));
}

// fp8 e4m3 MMA, K=32 (fragments byte-compatible with bf16 k16 layout)
__device__ __forceinline__ void mma32q(float* c, const uint32_t* a,
                                       uint32_t b0, uint32_t b1) {
    asm volatile(
        "mma.sync.aligned.m16n8k32.row.col.f32.e4m3.e4m3.f32 "
        "{%0,%1,%2,%3}, {%4,%5,%6,%7}, {%8,%9}, {%0,%1,%2,%3};"
        : "+f"(c[0]), "+f"(c[1]), "+f"(c[2]), "+f"(c[3])
        : "r"(a[0]), "r"(a[1]), "r"(a[2]), "r"(a[3]), "r"(b0), "r"(b1));
}

// ---------------- setup ----------------
// fused: degree count + fp8 feature copy + fp8 effective-weight prep
__global__ void k_pre(const float* __restrict__ feat, const int* __restrict__ dst,
                      const float* __restrict__ w11, const float* __restrict__ w21,
                      const float* __restrict__ w12, const float* __restrict__ w22) {
    int i = blockIdx.x * blockDim.x + threadIdx.x;
    if (i < NE) atomicAdd(&g_deg[dst[i]], 1);
    if (i < NN * DD / 4) {
        float4 v = __ldg((const float4*)feat + i);
        uint16_t p0 = fp8pack(v.x, v.y);
        uint16_t p1 = fp8pack(v.z, v.w);
        ((uint32_t*)g_f8)[i] = (uint32_t)p0 | ((uint32_t)p1 << 16);
    }
    if (i < DD * DD) {
        const float B1 = 0.6931471805599453f;  // log 2
        const float B2 = 0.4054651081081644f;  // log 1.5
        int n = i >> 7, k = i & 127;
        float ikn = (k == n) ? 1.f : 0.f;
        g_w1q[0][n * DD + k] = fp8one(B1 * w11[k * DD + n] + (1.f - B1) * ikn);
        g_w2q[0][n * DD + k] = fp8one(0.5f * (B1 * w21[k * DD + n] + (1.f - B1) * ikn));
        g_w1q[1][n * DD + k] = fp8one(B2 * w12[k * DD + n] + (1.f - B2) * ikn);
        g_w2q[1][n * DD + k] = fp8one(0.5f * (B2 * w22[k * DD + n] + (1.f - B2) * ikn));
    }
}

// fused scan: warp-shuffle block scan + lookback + norm/gcnt; re-zeros g_deg
__global__ void k_scan(const int* __restrict__ gids) {
    __shared__ int wsum[32];
    __shared__ int blockoff;
    int b = blockIdx.x, t = threadIdx.x;
    int wid = t >> 5, ln = t & 31;
    int i = b * 1024 + t;
    int v = (i < NN) ? g_deg[i] : 0;
    int x = v;
    #pragma unroll
    for (int o = 1; o < 32; o <<= 1) {
        int y = __shfl_up_sync(0xFFFFFFFFu, x, o);
        if (ln >= o) x += y;
    }
    if (ln == 31) wsum[wid] = x;
    __syncthreads();
    if (wid == 0) {
        int s = wsum[ln];
        #pragma unroll
        for (int o = 1; o < 32; o <<= 1) {
            int y = __shfl_up_sync(0xFFFFFFFFu, s, o);
            if (ln >= o) s += y;
        }
        wsum[ln] = s;
    }
    __syncthreads();
    int incl = x + (wid ? wsum[wid - 1] : 0);
    if (t == 1023)
        atomicExch(&g_agg[b], 0x80000000u | (unsigned)incl);
    if (t < 32) {
        int sum = 0;
        for (int base = 0; base < b; base += 32) {
            int idx = base + t;
            unsigned val = 0;
            if (idx < b) {
                do { val = *(volatile unsigned*)&g_agg[idx]; }
                while (!(val & 0x80000000u));
            }
            sum += (int)(val & 0x7FFFFFFFu);
        }
        #pragma unroll
        for (int o = 16; o > 0; o >>= 1)
            sum += __shfl_down_sync(0xFFFFFFFFu, sum, o);
        if (t == 0) blockoff = sum;
    }
    __syncthreads();
    if (i < NN) {
        g_off[i] = blockoff + incl - v;
        g_norm[i] = rsqrtf((float)(v + 1));   // +1 self loop
        g_deg[i] = 0;                         // restore zero for next replay
        atomicAdd(&g_gcnt[gids[i]], 1);
    }
    if (i == NN) g_off[NN] = NE;
}

// fused: CSR fill + fp8 norm⊙feature (from fp8 unscaled) + g_agg re-zero
__global__ void k_fill(const int* __restrict__ src, const int* __restrict__ dst) {
    int i = blockIdx.x * blockDim.x + threadIdx.x;
    if (i < NE) {
        int d = dst[i];
        int p = g_off[d] + atomicAdd(&g_fill[d], 1);
        g_csr[p] = src[i];
    }
    if (i < NN * DD / 4) {
        int node = i >> 5;                  // 32 words per 128-fp8 row
        float nrm = g_norm[node];
        uint32_t q = ((const uint32_t*)g_f8)[i];
        uint32_t h01, h23;
        fp8x4_to_h2x2(q, h01, h23);
        float2 a = h2f(h01), b = h2f(h23);
        uint16_t p0 = fp8pack(a.x * nrm, a.y * nrm);
        uint16_t p1 = fp8pack(b.x * nrm, b.y * nrm);
        ((uint32_t*)g_fs)[i] = (uint32_t)p0 | ((uint32_t)p1 << 16);
    }
    if (i < 128) g_agg[i] = 0u;             // restore zero (all scan readers done)
}

// ---- SpMM (fp8 gather, half2 accumulate): hs_fp8 = 0.5*nrm*(x̃[n]+Σx̃[src])
// 16-lane node groups (uint2 = 8 fp8/lane), 8-edge unroll. Re-zeros g_fill.
__global__ void k_spmm(const uint8_t* __restrict__ fin, uint8_t* __restrict__ fout) {
    int gt = blockIdx.x * blockDim.x + threadIdx.x;
    int node = gt >> 4, lane = gt & 15;
    if (node >= NN) return;
    if (lane == 0) g_fill[node] = 0;        // restore zero (idempotent on L2 call)
    const uint2* F = (const uint2*)fin;     // row = 128B = 16 x uint2
    uint2 a = __ldg(F + (size_t)node * 16 + lane);   // self loop (pre-scaled)
    uint32_t h[4];
    fp8x4_to_h2x2(a.x, h[0], h[1]);
    fp8x4_to_h2x2(a.y, h[2], h[3]);

    int beg = g_off[node], end = g_off[node + 1];
    int e = beg;
    for (; e + 8 <= end; e += 8) {
        uint2 v[8];
        #pragma unroll
        for (int j = 0; j < 8; j++) {
            int s = __ldg(g_csr + e + j);
            v[j] = __ldg(F + (size_t)s * 16 + lane);
        }
        #pragma unroll
        for (int j = 0; j < 8; j++) {
            uint32_t c0, c1, c2, c3;
            fp8x4_to_h2x2(v[j].x, c0, c1);
            fp8x4_to_h2x2(v[j].y, c2, c3);
            h[0] = hadd2(h[0], c0);
            h[1] = hadd2(h[1], c1);
            h[2] = hadd2(h[2], c2);
            h[3] = hadd2(h[3], c3);
        }
    }
    for (; e < end; e++) {
        int s = __ldg(g_csr + e);
        uint2 v0 = __ldg(F + (size_t)s * 16 + lane);
        uint32_t c0, c1, c2, c3;
        fp8x4_to_h2x2(v0.x, c0, c1);
        fp8x4_to_h2x2(v0.y, c2, c3);
        h[0] = hadd2(h[0], c0);
        h[1] = hadd2(h[1], c1);
        h[2] = hadd2(h[2], c2);
        h[3] = hadd2(h[3], c3);
    }
    float sc = 0.5f * g_norm[node];
    float2 f0 = h2f(h[0]), f1 = h2f(h[1]), f2 = h2f(h[2]), f3 = h2f(h[3]);
    uint16_t p0 = fp8pack(f0.x * sc, f0.y * sc);
    uint16_t p1 = fp8pack(f1.x * sc, f1.y * sc);
    uint16_t p2 = fp8pack(f2.x * sc, f2.y * sc);
    uint16_t p3 = fp8pack(f3.x * sc, f3.y * sc);
    uint2 o;
    o.x = (uint32_t)p0 | ((uint32_t)p1 << 16);
    o.y = (uint32_t)p2 | ((uint32_t)p3 << 16);
    ((uint2*)fout)[(size_t)node * 16 + lane] = o;
}

// ---- fp8 mma.sync GEMM: relu(hs@W1e + f0@W2e + b) -------------------------
// BM=128, BN=128, K=256 (hs|f0), 2 chunks of K=128 fp8 (128B SW128 rows),
// 8 warps (warp tile 32x64), both chunks prefetched, m16n8k32 e4m3.
// MODE 0: write fp8 norm⊙x1 (feeds L2 gather).
// MODE 1: pool into g_pooled; LAST BLOCK runs the decoder MLP inline.
template <int MODE>
__global__ void __launch_bounds__(256, 2)
k_mma(const uint8_t* __restrict__ Ahs, const uint8_t* __restrict__ Af0,
      const uint8_t* __restrict__ Bw1, const uint8_t* __restrict__ Bw2,
      const float* __restrict__ bias, uint8_t* __restrict__ x8out,
      const int* __restrict__ gids,
      const float* __restrict__ d1w, const float* __restrict__ d1b,
      const float* __restrict__ d2w, const float* __restrict__ d2b,
      float* __restrict__ out) {
    extern __shared__ float smem[];   // 2 chunks x (A 16KB + B 16KB)
    uint32_t sb = smem_u32(smem);
    int t = threadIdx.x, lane = t & 31, w = t >> 5;
    int wm = (w & 3) * 32, wn = (w >> 2) * 64;
    int R0 = blockIdx.x * 128;

    float acc[2][8][4];
    #pragma unroll
    for (int mt = 0; mt < 2; mt++)
        #pragma unroll
        for (int j = 0; j < 8; j++)
            #pragma unroll
            for (int q = 0; q < 4; q++) acc[mt][j][q] = 0.f;

    auto load_chunk = [&](int c) {
        uint32_t aB = sb + (uint32_t)c * 32768u;
        uint32_t bB = aB + 16384u;
        const uint8_t* A = c ? Af0 : Ahs;
        const uint8_t* B = c ? Bw2 : Bw1;
        #pragma unroll
        for (int i = 0; i < 4; i++) {
            int idx = i * 256 + t;
            int r = idx >> 3, f4 = idx & 7;
            int row = R0 + r; if (row >= NN) row = 0;
            uint32_t off = r * 128 + ((f4 * 16) ^ ((r & 7) << 4));
            cpa16(aB + off, A + (size_t)row * DD + f4 * 16);
            cpa16(bB + off, B + (size_t)r * DD + f4 * 16);
        }
        asm volatile("cp.async.commit_group;" ::: "memory");
    };

    load_chunk(0);
    load_chunk(1);

    int rA[2], rB[4];
    #pragma unroll
    for (int mt = 0; mt < 2; mt++)
        rA[mt] = wm + mt * 16 + (lane & 7) + ((lane >> 3) & 1) * 8;
    #pragma unroll
    for (int nt = 0; nt < 4; nt++)
        rB[nt] = wn + nt * 16 + (lane & 7) + ((lane >> 4) & 1) * 8;
    uint32_t aH = ((lane >> 4) & 1) * 16;
    uint32_t bH = ((lane >> 3) & 1) * 16;

    #pragma unroll
    for (int c = 0; c < 2; c++) {
        if (c == 0) asm volatile("cp.async.wait_group 1;" ::: "memory");
        else        asm volatile("cp.async.wait_group 0;" ::: "memory");
        __syncthreads();

        uint32_t aB = sb + (uint32_t)c * 32768u;
        uint32_t bB = aB + 16384u;
        #pragma unroll
        for (int kk = 0; kk < 4; kk++) {   // k32 per step, 4 steps = K 128 fp8
            uint32_t a[2][4], b[4][4];
            #pragma unroll
            for (int mt = 0; mt < 2; mt++)
                ldsm4(a[mt], aB + rA[mt] * 128 +
                              (((uint32_t)(kk * 32) + aH) ^ ((rA[mt] & 7) << 4)));
            #pragma unroll
            for (int nt = 0; nt < 4; nt++)
                ldsm4(b[nt], bB + rB[nt] * 128 +
                              (((uint32_t)(kk * 32) + bH) ^ ((rB[nt] & 7) << 4)));
            #pragma unroll
            for (int mt = 0; mt < 2; mt++)
                #pragma unroll
                for (int nt = 0; nt < 4; nt++) {
                    mma32q(acc[mt][2 * nt + 0], a[mt], b[nt][0], b[nt][1]);
                    mma32q(acc[mt][2 * nt + 1], a[mt], b[nt][2], b[nt][3]);
                }
        }
    }

    if (MODE == 0) {
        // epilogue: bias + relu + norm-prescale + fp8 pack
        #pragma unroll
        for (int mt = 0; mt < 2; mt++) {
            int row0 = R0 + wm + mt * 16 + (lane >> 2);
            float nr0 = (row0 < NN) ? g_norm[row0] : 0.f;
            float nr1 = (row0 + 8 < NN) ? g_norm[row0 + 8] : 0.f;
            #pragma unroll
            for (int j = 0; j < 8; j++) {
                int col = wn + j * 8 + (lane & 3) * 2;
                float2 bb = *(const float2*)(bias + col);
                float v0 = fmaxf(acc[mt][j][0] + bb.x, 0.f) * nr0;
                float v1 = fmaxf(acc[mt][j][1] + bb.y, 0.f) * nr0;
                float v2 = fmaxf(acc[mt][j][2] + bb.x, 0.f) * nr1;
                float v3 = fmaxf(acc[mt][j][3] + bb.y, 0.f) * nr1;
                if (row0 < NN)
                    *(uint16_t*)(x8out + (size_t)row0 * DD + col) = fp8pack(v0, v1);
                if (row0 + 8 < NN)
                    *(uint16_t*)(x8out + (size_t)(row0 + 8) * DD + col) = fp8pack(v2, v3);
            }
        }
    } else {
        // pooled epilogue: rows r0, r0+8, r0+16, r0+24 per thread
        int r0 = R0 + wm + (lane >> 2);
        int ra = r0, rb = r0 + 8, rc = r0 + 16, rd = r0 + 24;
        bool va = ra < NN, vb = rb < NN, vc = rc < NN, vd = rd < NN;
        if (va) {
            int ga = __ldg(gids + ra);
            int gb = vb ? __ldg(gids + rb) : ga;
            int gc = vc ? __ldg(gids + rc) : ga;
            int gd = vd ? __ldg(gids + rd) : ga;
            bool same = (ga == gb) && (gb == gc) && (gc == gd);
            #pragma unroll
            for (int j = 0; j < 8; j++) {
                int col = wn + j * 8 + (lane & 3) * 2;
                float2 bb = *(const float2*)(bias + col);
                #pragma unroll
                for (int q = 0; q < 2; q++) {
                    float bq = q ? bb.y : bb.x;
                    float u0 = va ? fmaxf(acc[0][j][q + 0] + bq, 0.f) : 0.f;
                    float u1 = vb ? fmaxf(acc[0][j][q + 2] + bq, 0.f) : 0.f;
                    float u2 = vc ? fmaxf(acc[1][j][q + 0] + bq, 0.f) : 0.f;
                    float u3 = vd ? fmaxf(acc[1][j][q + 2] + bq, 0.f) : 0.f;
                    if (same) {
                        atomicAdd(&g_pooled[ga * DD + col + q], u0 + u1 + u2 + u3);
                    } else {
                        atomicAdd(&g_pooled[ga * DD + col + q], u0);
                        if (vb) atomicAdd(&g_pooled[gb * DD + col + q], u1);
                        if (vc) atomicAdd(&g_pooled[gc * DD + col + q], u2);
                        if (vd) atomicAdd(&g_pooled[gd * DD + col + q], u3);
                    }
                }
            }
        }

        // ---- last-block-done: run the decoder MLP inline ----
        __shared__ int is_last;
        __threadfence();
        __syncthreads();
        if (t == 0) {
            int v = atomicAdd(&g_ctr, 1);
            is_last = (v == NTILES - 1);
            if (is_last) g_ctr = 0;          // restore zero for next replay
        }
        __syncthreads();
        if (is_last) {
            __threadfence();                 // see all blocks' pooled atomics
            int b = t;
            if (b < NG) {
                float inv = 1.f / fmaxf((float)g_gcnt[b], 1.f);
                float h[PHH];
                #pragma unroll
                for (int p = 0; p < PHH; p++) h[p] = __ldg(d1b + p);
                for (int c2 = 0; c2 < DD; c2++) {
                    float a2 = g_pooled[b * DD + c2] * inv;
                    g_pooled[b * DD + c2] = 0.f;   // restore zero
                    #pragma unroll
                    for (int p = 0; p < PHH; p++)
                        h[p] = fmaf(a2, __ldg(d1w + c2 * PHH + p), h[p]);
                }
                g_gcnt[b] = 0;                     // restore zero
                float z = __ldg(d2b);
                #pragma unroll
                for (int p = 0; p < PHH; p++)
                    z = fmaf(fmaxf(h[p], 0.f), __ldg(d2w + p), z);
                out[b] = 1.f / (1.f + expf(-z));
            }
        }
    }
}

// ---------------- launch ----------------
extern "C" void kernel_launch(void* const* d_in, const int* in_sizes, int n_in,
                              void* d_out, int out_size) {
    const float* feature = (const float*)d_in[0];
    const int*   src     = (const int*)d_in[1];
    const int*   dst     = (const int*)d_in[2];
    const int*   gids    = (const int*)d_in[3];
    const float* w1_1    = (const float*)d_in[4];
    const float* w2_1    = (const float*)d_in[5];
    const float* b_1     = (const float*)d_in[6];
    const float* w1_2    = (const float*)d_in[7];
    const float* w2_2    = (const float*)d_in[8];
    const float* b_2     = (const float*)d_in[9];
    const float* d1w     = (const float*)d_in[10];
    const float* d1b     = (const float*)d_in[11];
    const float* d2w     = (const float*)d_in[12];
    const float* d2b     = (const float*)d_in[13];
    float* out = (float*)d_out;

    uint8_t *f8_p = nullptr, *fs_p = nullptr, *xs_p = nullptr, *h8_p = nullptr;
    uint8_t *w1q_p = nullptr, *w2q_p = nullptr;
    cudaGetSymbolAddress((void**)&f8_p,   g_f8);
    cudaGetSymbolAddress((void**)&fs_p,   g_fs);
    cudaGetSymbolAddress((void**)&xs_p,   g_xs);
    cudaGetSymbolAddress((void**)&h8_p,   g_h8);
    cudaGetSymbolAddress((void**)&w1q_p,  g_w1q);
    cudaGetSymbolAddress((void**)&w2q_p,  g_w2q);

    const int SMEM_MMA = 65536;   // 2 chunks x (A 16KB + B 16KB)
    cudaFuncSetAttribute(k_mma<0>, cudaFuncAttributeMaxDynamicSharedMemorySize, SMEM_MMA);
    cudaFuncSetAttribute(k_mma<1>, cudaFuncAttributeMaxDynamicSharedMemorySize, SMEM_MMA);

    k_pre<<<(NN * DD / 4 + 255) / 256, 256>>>(feature, dst, w1_1, w2_1, w1_2, w2_2);
    k_scan<<<NSB, 1024>>>(gids);
    k_fill<<<(NN * DD / 4 + 255) / 256, 256>>>(src, dst);

    // layer 1: spmm gathers fp8 norm⊙feature -> hs (fp8);
    //          gemm (h8, f8) -> fp8 norm⊙x1
    k_spmm<<<(NN * 16 + 255) / 256, 256>>>(fs_p, h8_p);
    k_mma<0><<<NTILES, 256, SMEM_MMA>>>(h8_p, f8_p, w1q_p, w2q_p, b_1, xs_p, gids,
                                        nullptr, nullptr, nullptr, nullptr, nullptr);
    // layer 2: spmm gathers fp8 norm⊙x1 -> hs (fp8);
    //          gemm (h8, f8) pools into g_pooled; last block runs decoder MLP
    k_spmm<<<(NN * 16 + 255) / 256, 256>>>(xs_p, h8_p);
    k_mma<1><<<NTILES, 256, SMEM_MMA>>>(h8_p, f8_p,
                                        w1q_p + DD * DD, w2q_p + DD * DD, b_2,
                                        nullptr, gids, d1w, d1b, d2w, d2b, out);
}